// round 6
// baseline (speedup 1.0000x reference)
#include <cuda_runtime.h>

#define NROWS 204800
#define BN_EPS 1e-5f

#define FD0 100000
#define FD1 1000
#define FD2 100
#define FD3 50
#define PV (FD0 + FD1 + FD2 + FD3)
#define P_OFF1 (FD0 * 64)
#define P_OFF2 ((FD0 + FD1) * 64)
#define P_OFF3 ((FD0 + FD1 + FD2) * 64)

#define K1_BLOCKS 1024
#define K3_GRID 444
#define K5_GRID 444
#define SETUP_BLOCKS 512
#define TILE_R 128
#define N_TILES (NROWS / TILE_R)   // 1600

typedef unsigned long long u64;

// packed fp32x2 fused multiply-add: one instr, two MACs (FFMA2)
__device__ __forceinline__ u64 fma2(u64 a, u64 b, u64 c) {
    u64 d;
    asm("fma.rn.f32x2 %0, %1, %2, %3;" : "=l"(d) : "l"(a), "l"(b), "l"(c));
    return d;
}
__device__ __forceinline__ float f32x2_sum(u64 v) {
    float lo = __uint_as_float((unsigned)v);
    float hi = __uint_as_float((unsigned)(v >> 32));
    return lo + hi;
}

// Scratch (device globals; no runtime allocation allowed)
__device__ float g_P[PV * 64];                    // precomputed emb_i @ w1_block_i^T
__device__ float g_A[64 * 8];                     // cont_w folded into w1
__device__ float g_cb[64];                        // b1 + cont_b folded into w1
__device__ float g_h1[(size_t)NROWS * 64];        // pre-BN layer-1 activations
__device__ float g_h2[(size_t)NROWS * 32];        // pre-BN layer-2 activations
__device__ float g_part1[K1_BLOCKS * 128];        // per-block BN1 partials
__device__ float g_part2[K3_GRID * 64];           // per-block BN2 partials
__device__ float g_bn1[128];                      // scale[64], shift[64]
__device__ float g_bn2[64];                       // scale[32], shift[32]
__device__ unsigned g_cnt1 = 0;
__device__ unsigned g_cnt2 = 0;

// ---------------------------------------------------------------------------
// kSetup: cont-fold init AND all four P tables in one launch.
// ---------------------------------------------------------------------------
__global__ void __launch_bounds__(256) kSetup(
    const float* __restrict__ emb0, const float* __restrict__ emb1,
    const float* __restrict__ emb2, const float* __restrict__ emb3,
    const float* __restrict__ w1, const float* __restrict__ b1,
    const float* __restrict__ cont_w, const float* __restrict__ cont_b) {
    int bid = blockIdx.x;
    int lane = threadIdx.x & 31;
    int warp = threadIdx.x >> 5;

    if (bid == 511) {  // cont-feature fold into w1
        int j = threadIdx.x;
        if (j < 64) {
            float cb = b1[j];
            for (int c = 0; c < 8; c++) {
                float a = 0.f;
#pragma unroll
                for (int d = 0; d < 32; d++) {
                    float w = w1[j * 384 + (4 + c) * 32 + d];
                    a = fmaf(cont_w[c * 32 + d], w, a);
                    cb = fmaf(cont_b[c * 32 + d], w, cb);
                }
                g_A[j * 8 + c] = a;
            }
            g_cb[j] = cb;
        }
        return;
    }

    const float* emb;
    int V, pOff, colOff, wfirst, nwarp;
    if (bid < 506) {
        emb = emb0; V = FD0; pOff = 0; colOff = 0;
        wfirst = bid * 8 + warp; nwarp = 506 * 8;
    } else if (bid < 510) {
        emb = emb1; V = FD1; pOff = P_OFF1; colOff = 32;
        wfirst = (bid - 506) * 8 + warp; nwarp = 32;
    } else if (warp < 4) {
        emb = emb2; V = FD2; pOff = P_OFF2; colOff = 64;
        wfirst = warp; nwarp = 4;
    } else {
        emb = emb3; V = FD3; pOff = P_OFF3; colOff = 96;
        wfirst = warp - 4; nwarp = 4;
    }

    float wa[32], wb[32];
#pragma unroll
    for (int d = 0; d < 32; d++) {
        wa[d] = w1[lane * 384 + colOff + d];
        wb[d] = w1[(lane + 32) * 384 + colOff + d];
    }
    for (int v = wfirst; v < V; v += nwarp) {
        float ev = emb[v * 32 + lane];
        float a0 = 0.f, a1 = 0.f;
#pragma unroll
        for (int d = 0; d < 32; d++) {
            float e = __shfl_sync(0xffffffffu, ev, d);
            a0 = fmaf(e, wa[d], a0);
            a1 = fmaf(e, wb[d], a1);
        }
        g_P[pOff + v * 64 + lane] = a0;
        g_P[pOff + v * 64 + 32 + lane] = a1;
    }
}

// ---------------------------------------------------------------------------
// Kernel 1: 2 rows per warp iteration (doubled gather MLP).
// FM interaction + linear -> out; h1 -> g_h1; BN1 partials; last block
// finalizes BN1.
// ---------------------------------------------------------------------------
__global__ void __launch_bounds__(256) k1(
    const float* __restrict__ x,
    const float* __restrict__ emb0, const float* __restrict__ emb1,
    const float* __restrict__ emb2, const float* __restrict__ emb3,
    const float* __restrict__ lin0, const float* __restrict__ lin1,
    const float* __restrict__ lin2, const float* __restrict__ lin3,
    const float* __restrict__ cont_w, const float* __restrict__ cont_b,
    const float* __restrict__ clin_w, const float* __restrict__ clin_b,
    const float* __restrict__ fin_bias,
    const float* __restrict__ g1, const float* __restrict__ beta1,
    float* __restrict__ out) {
    int lane = threadIdx.x & 31;
    int warp = threadIdx.x >> 5;
    int gw = blockIdx.x * 8 + warp;
    const int nw = K1_BLOCKS * 8;
    const int NPAIR = NROWS / 2;

    float cw[8], cbv[8], clw[8], clb[8], A0[8], A1[8];
#pragma unroll
    for (int c = 0; c < 8; c++) {
        cw[c] = cont_w[c * 32 + lane];
        cbv[c] = cont_b[c * 32 + lane];
        clw[c] = clin_w[c * 32 + lane];
        clb[c] = clin_b[c * 32 + lane];
        A0[c] = g_A[lane * 8 + c];
        A1[c] = g_A[(lane + 32) * 8 + c];
    }
    float finb = fin_bias[lane];
    float cb0 = g_cb[lane], cb1 = g_cb[lane + 32];
    float sum0 = 0.f, sq0 = 0.f, sum1 = 0.f, sq1 = 0.f;

    for (int pr = gw; pr < NPAIR; pr += nw) {
        int rA = pr * 2;
        int rB = rA + 1;
        float xv = 0.f;
        if (lane < 24) xv = x[rA * 12 + lane];
        int iA0 = (int)__shfl_sync(0xffffffffu, xv, 0);
        int iA1 = (int)__shfl_sync(0xffffffffu, xv, 1);
        int iA2 = (int)__shfl_sync(0xffffffffu, xv, 2);
        int iA3 = (int)__shfl_sync(0xffffffffu, xv, 3);
        int iB0 = (int)__shfl_sync(0xffffffffu, xv, 12);
        int iB1 = (int)__shfl_sync(0xffffffffu, xv, 13);
        int iB2 = (int)__shfl_sync(0xffffffffu, xv, 14);
        int iB3 = (int)__shfl_sync(0xffffffffu, xv, 15);
        float xcA[8], xcB[8];
#pragma unroll
        for (int c = 0; c < 8; c++) {
            xcA[c] = __shfl_sync(0xffffffffu, xv, 4 + c);
            xcB[c] = __shfl_sync(0xffffffffu, xv, 16 + c);
        }

        // issue all gathers (16 independent loads)
        float eA0 = emb0[iA0 * 32 + lane], eB0 = emb0[iB0 * 32 + lane];
        float eA1 = emb1[iA1 * 32 + lane], eB1 = emb1[iB1 * 32 + lane];
        float eA2 = emb2[iA2 * 32 + lane], eB2 = emb2[iB2 * 32 + lane];
        float eA3 = emb3[iA3 * 32 + lane], eB3 = emb3[iB3 * 32 + lane];
        float lA = finb + lin0[iA0 * 32 + lane] + lin1[iA1 * 32 + lane] +
                   lin2[iA2 * 32 + lane] + lin3[iA3 * 32 + lane];
        float lB = finb + lin0[iB0 * 32 + lane] + lin1[iB1 * 32 + lane] +
                   lin2[iB2 * 32 + lane] + lin3[iB3 * 32 + lane];
        float pA0a = g_P[iA0 * 64 + lane],        pA0b = g_P[iA0 * 64 + 32 + lane];
        float pA1a = g_P[P_OFF1 + iA1 * 64 + lane], pA1b = g_P[P_OFF1 + iA1 * 64 + 32 + lane];
        float pA2a = g_P[P_OFF2 + iA2 * 64 + lane], pA2b = g_P[P_OFF2 + iA2 * 64 + 32 + lane];
        float pA3a = g_P[P_OFF3 + iA3 * 64 + lane], pA3b = g_P[P_OFF3 + iA3 * 64 + 32 + lane];
        float pB0a = g_P[iB0 * 64 + lane],        pB0b = g_P[iB0 * 64 + 32 + lane];
        float pB1a = g_P[P_OFF1 + iB1 * 64 + lane], pB1b = g_P[P_OFF1 + iB1 * 64 + 32 + lane];
        float pB2a = g_P[P_OFF2 + iB2 * 64 + lane], pB2b = g_P[P_OFF2 + iB2 * 64 + 32 + lane];
        float pB3a = g_P[P_OFF3 + iB3 * 64 + lane], pB3b = g_P[P_OFF3 + iB3 * 64 + 32 + lane];

        // row A
        {
            float s = eA0 + eA1 + eA2 + eA3;
            float sq = eA0 * eA0 + eA1 * eA1 + eA2 * eA2 + eA3 * eA3;
            float lin = lA;
#pragma unroll
            for (int c = 0; c < 8; c++) {
                float e = fmaf(xcA[c], cw[c], cbv[c]);
                s += e;
                sq = fmaf(e, e, sq);
                lin += fmaf(xcA[c], clw[c], clb[c]);
            }
            out[rA * 32 + lane] = lin + 0.5f * (s * s - sq);
            float a0 = cb0 + pA0a + pA1a + pA2a + pA3a;
            float a1 = cb1 + pA0b + pA1b + pA2b + pA3b;
#pragma unroll
            for (int c = 0; c < 8; c++) {
                a0 = fmaf(xcA[c], A0[c], a0);
                a1 = fmaf(xcA[c], A1[c], a1);
            }
            g_h1[(size_t)rA * 64 + lane] = a0;
            g_h1[(size_t)rA * 64 + 32 + lane] = a1;
            sum0 += a0; sq0 = fmaf(a0, a0, sq0);
            sum1 += a1; sq1 = fmaf(a1, a1, sq1);
        }
        // row B
        {
            float s = eB0 + eB1 + eB2 + eB3;
            float sq = eB0 * eB0 + eB1 * eB1 + eB2 * eB2 + eB3 * eB3;
            float lin = lB;
#pragma unroll
            for (int c = 0; c < 8; c++) {
                float e = fmaf(xcB[c], cw[c], cbv[c]);
                s += e;
                sq = fmaf(e, e, sq);
                lin += fmaf(xcB[c], clw[c], clb[c]);
            }
            out[rB * 32 + lane] = lin + 0.5f * (s * s - sq);
            float a0 = cb0 + pB0a + pB1a + pB2a + pB3a;
            float a1 = cb1 + pB0b + pB1b + pB2b + pB3b;
#pragma unroll
            for (int c = 0; c < 8; c++) {
                a0 = fmaf(xcB[c], A0[c], a0);
                a1 = fmaf(xcB[c], A1[c], a1);
            }
            g_h1[(size_t)rB * 64 + lane] = a0;
            g_h1[(size_t)rB * 64 + 32 + lane] = a1;
            sum0 += a0; sq0 = fmaf(a0, a0, sq0);
            sum1 += a1; sq1 = fmaf(a1, a1, sq1);
        }
    }

    __shared__ float rs[64][8], rq[64][8];
    rs[lane][warp] = sum0; rs[lane + 32][warp] = sum1;
    rq[lane][warp] = sq0;  rq[lane + 32][warp] = sq1;
    __syncthreads();
    int t = threadIdx.x;
    if (t < 64) {
        float a = 0.f;
#pragma unroll
        for (int w = 0; w < 8; w++) a += rs[t][w];
        g_part1[blockIdx.x * 128 + t] = a;
    } else if (t < 128) {
        float a = 0.f;
#pragma unroll
        for (int w = 0; w < 8; w++) a += rq[t - 64][w];
        g_part1[blockIdx.x * 128 + t] = a;
    }

    __threadfence();
    __shared__ unsigned s_last;
    if (t == 0) {
        unsigned tk = atomicAdd(&g_cnt1, 1u);
        s_last = (tk == gridDim.x - 1) ? 1u : 0u;
    }
    __syncthreads();
    if (s_last) {
        __shared__ float sm[256];
        int ch = t & 127;
        int half = t >> 7;
        float a = 0.f;
        int b0 = half * (K1_BLOCKS / 2);
        for (int b = b0; b < b0 + K1_BLOCKS / 2; b++) a += g_part1[b * 128 + ch];
        sm[t] = a;
        __syncthreads();
        if (t < 64) {
            float s = sm[t] + sm[128 + t];
            float q = sm[64 + t] + sm[192 + t];
            float mean = s / (float)NROWS;
            float var = q / (float)NROWS - mean * mean;
            float scale = g1[t] * rsqrtf(var + BN_EPS);
            g_bn1[t] = scale;
            g_bn1[64 + t] = beta1[t] - mean * scale;
        }
        if (t == 0) g_cnt1 = 0;
    }
}

// ---------------------------------------------------------------------------
// Kernel 3: smem-tiled GEMM with packed fp32x2 FMA (FFMA2).
// h2 = relu(bn1(h1)) @ w2^T + b2. w2 is [32 out, 64 K]. Weights staged
// K-pair-packed: wt2[kq*32+c] = float4{w2[c][4kq..4kq+3]} (= 2 packed pairs).
// Thread owns 4 rows x cols {tj, tj+8, tj+16, tj+24}. Accumulate packed
// over K; horizontal add in epilogue. BN2 partials; last block finalizes.
// ---------------------------------------------------------------------------
__global__ void __launch_bounds__(256) k3(const float* __restrict__ w2,
                                          const float* __restrict__ b2,
                                          const float* __restrict__ g2,
                                          const float* __restrict__ beta2) {
    __shared__ float a[TILE_R * 68];       // bn+relu(h1) tile, stride 68
    __shared__ ulonglong2 wt2[16 * 32];    // [kq][c], K=64 -> 16 kq, 32 cols
    __shared__ float sc[64], sh[64];
    __shared__ float wsum[8 * 32], wsq[8 * 32];

    int tid = threadIdx.x;
    int lane = tid & 31, warp = tid >> 5;
    int tr = lane >> 3, tj = lane & 7;

    // stage w2 (32x64 floats = 512 float4s) K-pair-packed transposed
    for (int i = tid; i < 512; i += 256) {
        int c = i >> 4, kq = i & 15;   // c in [0,32), kq in [0,16)
        float4 v = *(const float4*)&w2[c * 64 + kq * 4];
        *(float4*)&wt2[kq * 32 + c] = v;
    }
    if (tid < 64) { sc[tid] = g_bn1[tid]; sh[tid] = g_bn1[64 + tid]; }
    float bj[4];
#pragma unroll
    for (int cc = 0; cc < 4; cc++) bj[cc] = b2[tj + 8 * cc];
    __syncthreads();

    float lsum[4] = {0.f, 0.f, 0.f, 0.f}, lsq[4] = {0.f, 0.f, 0.f, 0.f};
    int rbase = warp * 16 + tr;

    for (int tile = blockIdx.x; tile < N_TILES; tile += gridDim.x) {
        size_t base = (size_t)tile * TILE_R;
        // stage: bn1 + relu applied, float4 in/out
        for (int i = tid; i < TILE_R * 16; i += 256) {
            int r = i >> 4, c4 = (i & 15) * 4;
            float4 v = *(const float4*)&g_h1[(base + r) * 64 + c4];
            v.x = fmaxf(fmaf(v.x, sc[c4], sh[c4]), 0.f);
            v.y = fmaxf(fmaf(v.y, sc[c4 + 1], sh[c4 + 1]), 0.f);
            v.z = fmaxf(fmaf(v.z, sc[c4 + 2], sh[c4 + 2]), 0.f);
            v.w = fmaxf(fmaf(v.w, sc[c4 + 3], sh[c4 + 3]), 0.f);
            *(float4*)&a[r * 68 + c4] = v;
        }
        __syncthreads();

        u64 accp[4][4];
#pragma unroll
        for (int i = 0; i < 4; i++)
#pragma unroll
            for (int cc = 0; cc < 4; cc++) accp[i][cc] = 0ull;

#pragma unroll
        for (int kq = 0; kq < 16; kq++) {
            ulonglong2 w0 = wt2[kq * 32 + tj];
            ulonglong2 w1v = wt2[kq * 32 + tj + 8];
            ulonglong2 w2v = wt2[kq * 32 + tj + 16];
            ulonglong2 w3v = wt2[kq * 32 + tj + 24];
#pragma unroll
            for (int i = 0; i < 4; i++) {
                ulonglong2 av = *(ulonglong2*)&a[(rbase + i * 4) * 68 + kq * 4];
                accp[i][0] = fma2(av.x, w0.x, accp[i][0]);
                accp[i][0] = fma2(av.y, w0.y, accp[i][0]);
                accp[i][1] = fma2(av.x, w1v.x, accp[i][1]);
                accp[i][1] = fma2(av.y, w1v.y, accp[i][1]);
                accp[i][2] = fma2(av.x, w2v.x, accp[i][2]);
                accp[i][2] = fma2(av.y, w2v.y, accp[i][2]);
                accp[i][3] = fma2(av.x, w3v.x, accp[i][3]);
                accp[i][3] = fma2(av.y, w3v.y, accp[i][3]);
            }
        }

#pragma unroll
        for (int i = 0; i < 4; i++) {
            size_t r = base + rbase + i * 4;
#pragma unroll
            for (int cc = 0; cc < 4; cc++) {
                float v = f32x2_sum(accp[i][cc]) + bj[cc];
                g_h2[r * 32 + tj + 8 * cc] = v;
                lsum[cc] += v;
                lsq[cc] = fmaf(v, v, lsq[cc]);
            }
        }
        __syncthreads();
    }

    // reduce BN2 partials over tr groups (lanes xor 8,16), then across warps
#pragma unroll
    for (int cc = 0; cc < 4; cc++) {
        lsum[cc] += __shfl_xor_sync(0xffffffffu, lsum[cc], 8);
        lsum[cc] += __shfl_xor_sync(0xffffffffu, lsum[cc], 16);
        lsq[cc] += __shfl_xor_sync(0xffffffffu, lsq[cc], 8);
        lsq[cc] += __shfl_xor_sync(0xffffffffu, lsq[cc], 16);
    }
    if (tr == 0) {
#pragma unroll
        for (int cc = 0; cc < 4; cc++) {
            wsum[warp * 32 + tj + 8 * cc] = lsum[cc];
            wsq[warp * 32 + tj + 8 * cc] = lsq[cc];
        }
    }
    __syncthreads();
    int t = tid;
    if (t < 32) {
        float s = 0.f;
#pragma unroll
        for (int w = 0; w < 8; w++) s += wsum[w * 32 + t];
        g_part2[blockIdx.x * 64 + t] = s;
    } else if (t < 64) {
        float q = 0.f;
#pragma unroll
        for (int w = 0; w < 8; w++) q += wsq[w * 32 + (t - 32)];
        g_part2[blockIdx.x * 64 + t] = q;
    }

    __threadfence();
    __shared__ unsigned s_last;
    if (t == 0) {
        unsigned tk = atomicAdd(&g_cnt2, 1u);
        s_last = (tk == gridDim.x - 1) ? 1u : 0u;
    }
    __syncthreads();
    if (s_last) {
        __shared__ float sm[256];
        int ch = t & 63;
        int sl = t >> 6;  // 4 slices of K3_GRID/4
        float aa = 0.f;
        int b0 = sl * (K3_GRID / 4);
        for (int b = b0; b < b0 + K3_GRID / 4; b++) aa += g_part2[b * 64 + ch];
        sm[t] = aa;
        __syncthreads();
        if (t < 32) {
            float s = (sm[t] + sm[64 + t]) + (sm[128 + t] + sm[192 + t]);
            float q = (sm[32 + t] + sm[96 + t]) + (sm[160 + t] + sm[224 + t]);
            float mean = s / (float)NROWS;
            float var = q / (float)NROWS - mean * mean;
            float scale = g2[t] * rsqrtf(var + BN_EPS);
            g_bn2[t] = scale;
            g_bn2[32 + t] = beta2[t] - mean * scale;
        }
        if (t == 0) g_cnt2 = 0;
    }
}

// ---------------------------------------------------------------------------
// Kernel 5: smem-tiled GEMM, FFMA2. out += relu(bn2(h2)) @ w_out^T + b_out.
// w_out is [32 out, 32 K] = 256 float4s.
// ---------------------------------------------------------------------------
__global__ void __launch_bounds__(256) k5(const float* __restrict__ wout,
                                          const float* __restrict__ bout,
                                          float* __restrict__ out) {
    __shared__ float a[TILE_R * 36];      // bn+relu(h2) tile, stride 36
    __shared__ ulonglong2 wt2[8 * 32];    // [kq][c], K=32 -> 8 kq
    __shared__ float sc[32], sh[32];

    int tid = threadIdx.x;
    int lane = tid & 31, warp = tid >> 5;
    int tr = lane >> 3, tj = lane & 7;

    for (int i = tid; i < 256; i += 256) {
        int c = i >> 3, kq = i & 7;   // c in [0,32), kq in [0,8)
        float4 v = *(const float4*)&wout[c * 32 + kq * 4];
        *(float4*)&wt2[kq * 32 + c] = v;
    }
    if (tid < 32) { sc[tid] = g_bn2[tid]; sh[tid] = g_bn2[32 + tid]; }
    float bj[4];
#pragma unroll
    for (int cc = 0; cc < 4; cc++) bj[cc] = bout[tj + 8 * cc];
    __syncthreads();

    int rbase = warp * 16 + tr;

    for (int tile = blockIdx.x; tile < N_TILES; tile += gridDim.x) {
        size_t base = (size_t)tile * TILE_R;
        for (int i = tid; i < TILE_R * 8; i += 256) {
            int r = i >> 3, c4 = (i & 7) * 4;
            float4 v = *(const float4*)&g_h2[(base + r) * 32 + c4];
            v.x = fmaxf(fmaf(v.x, sc[c4], sh[c4]), 0.f);
            v.y = fmaxf(fmaf(v.y, sc[c4 + 1], sh[c4 + 1]), 0.f);
            v.z = fmaxf(fmaf(v.z, sc[c4 + 2], sh[c4 + 2]), 0.f);
            v.w = fmaxf(fmaf(v.w, sc[c4 + 3], sh[c4 + 3]), 0.f);
            *(float4*)&a[r * 36 + c4] = v;
        }
        __syncthreads();

        u64 accp[4][4];
#pragma unroll
        for (int i = 0; i < 4; i++)
#pragma unroll
            for (int cc = 0; cc < 4; cc++) accp[i][cc] = 0ull;

#pragma unroll
        for (int kq = 0; kq < 8; kq++) {
            ulonglong2 w0 = wt2[kq * 32 + tj];
            ulonglong2 w1v = wt2[kq * 32 + tj + 8];
            ulonglong2 w2v = wt2[kq * 32 + tj + 16];
            ulonglong2 w3v = wt2[kq * 32 + tj + 24];
#pragma unroll
            for (int i = 0; i < 4; i++) {
                ulonglong2 av = *(ulonglong2*)&a[(rbase + i * 4) * 36 + kq * 4];
                accp[i][0] = fma2(av.x, w0.x, accp[i][0]);
                accp[i][0] = fma2(av.y, w0.y, accp[i][0]);
                accp[i][1] = fma2(av.x, w1v.x, accp[i][1]);
                accp[i][1] = fma2(av.y, w1v.y, accp[i][1]);
                accp[i][2] = fma2(av.x, w2v.x, accp[i][2]);
                accp[i][2] = fma2(av.y, w2v.y, accp[i][2]);
                accp[i][3] = fma2(av.x, w3v.x, accp[i][3]);
                accp[i][3] = fma2(av.y, w3v.y, accp[i][3]);
            }
        }

#pragma unroll
        for (int i = 0; i < 4; i++) {
            size_t r = base + rbase + i * 4;
#pragma unroll
            for (int cc = 0; cc < 4; cc++) {
                int c = tj + 8 * cc;
                out[r * 32 + c] += f32x2_sum(accp[i][cc]) + bj[cc];
            }
        }
        __syncthreads();
    }
}

// ---------------------------------------------------------------------------
// Input order (setup_inputs dict insertion): x, emb0, lin0, emb1, lin1,
// emb2, lin2, emb3, lin3, cont_w, cont_b, clin_w, clin_b, fin_bias,
// w1, b1, g1, beta1, w2, b2, g2, beta2, w_out, b_out
// ---------------------------------------------------------------------------
extern "C" void kernel_launch(void* const* d_in, const int* in_sizes, int n_in,
                              void* d_out, int out_size) {
    const float* x      = (const float*)d_in[0];
    const float* emb0   = (const float*)d_in[1];
    const float* lin0   = (const float*)d_in[2];
    const float* emb1   = (const float*)d_in[3];
    const float* lin1   = (const float*)d_in[4];
    const float* emb2   = (const float*)d_in[5];
    const float* lin2   = (const float*)d_in[6];
    const float* emb3   = (const float*)d_in[7];
    const float* lin3   = (const float*)d_in[8];
    const float* cont_w = (const float*)d_in[9];
    const float* cont_b = (const float*)d_in[10];
    const float* clin_w = (const float*)d_in[11];
    const float* clin_b = (const float*)d_in[12];
    const float* fin_b  = (const float*)d_in[13];
    const float* w1     = (const float*)d_in[14];
    const float* b1     = (const float*)d_in[15];
    const float* g1     = (const float*)d_in[16];
    const float* beta1  = (const float*)d_in[17];
    const float* w2     = (const float*)d_in[18];
    const float* b2     = (const float*)d_in[19];
    const float* g2     = (const float*)d_in[20];
    const float* beta2  = (const float*)d_in[21];
    const float* w_out  = (const float*)d_in[22];
    const float* b_out  = (const float*)d_in[23];
    float* out = (float*)d_out;

    kSetup<<<SETUP_BLOCKS, 256>>>(emb0, emb1, emb2, emb3, w1, b1, cont_w, cont_b);
    k1<<<K1_BLOCKS, 256>>>(x, emb0, emb1, emb2, emb3, lin0, lin1, lin2, lin3,
                           cont_w, cont_b, clin_w, clin_b, fin_b, g1, beta1, out);
    k3<<<K3_GRID, 256>>>(w2, b2, g2, beta2);
    k5<<<K5_GRID, 256>>>(w_out, b_out, out);
}